// round 3
// baseline (speedup 1.0000x reference)
#include <cuda_runtime.h>
#include <cuda_fp16.h>
#include <cstdint>

// Problem shape (fixed by dataset)
#define M_TOKENS (4 * 4096)   // 16384
#define K_DIM    2048
#define N_DIM    2048
#define EPS      1e-7f

// Scratch (device globals: no allocations allowed in kernel_launch)
__device__ int8_t g_q[(size_t)M_TOKENS * K_DIM];   // quantized activations [M, K]
__device__ float  g_scales[M_TOKENS];              // per-token scales
__device__ int8_t g_w[(size_t)N_DIM * K_DIM];      // weights packed to int8 [N, K]

// ---------------------------------------------------------------------------
// Kernel 0: pack int32-marshalled weights down to int8.
// ---------------------------------------------------------------------------
__global__ __launch_bounds__(256) void pack_w_kernel(const int* __restrict__ w32) {
    const int idx = blockIdx.x * blockDim.x + threadIdx.x;  // group of 4 elements
    int4 v = reinterpret_cast<const int4*>(w32)[idx];
    char4 c = make_char4((char)v.x, (char)v.y, (char)v.z, (char)v.w);
    reinterpret_cast<char4*>(g_w)[idx] = c;
}

// ---------------------------------------------------------------------------
// Kernel 1: per-token dynamic int8 quantization.
// ---------------------------------------------------------------------------
__global__ __launch_bounds__(256) void quant_kernel(const float* __restrict__ x) {
    const int token = blockIdx.x;
    const int tid = threadIdx.x;
    const int lane = tid & 31;
    const int warp = tid >> 5;

    const float4* xr = reinterpret_cast<const float4*>(x + (size_t)token * K_DIM);
    float4 v0 = xr[tid * 2 + 0];
    float4 v1 = xr[tid * 2 + 1];

    float m = fabsf(v0.x);
    m = fmaxf(m, fabsf(v0.y)); m = fmaxf(m, fabsf(v0.z)); m = fmaxf(m, fabsf(v0.w));
    m = fmaxf(m, fabsf(v1.x)); m = fmaxf(m, fabsf(v1.y));
    m = fmaxf(m, fabsf(v1.z)); m = fmaxf(m, fabsf(v1.w));

    #pragma unroll
    for (int off = 16; off > 0; off >>= 1)
        m = fmaxf(m, __shfl_xor_sync(0xFFFFFFFFu, m, off));

    __shared__ float wmax[8];
    if (lane == 0) wmax[warp] = m;
    __syncthreads();
    if (warp == 0) {
        float t = (lane < 8) ? wmax[lane] : 0.0f;
        #pragma unroll
        for (int off = 4; off > 0; off >>= 1)
            t = fmaxf(t, __shfl_xor_sync(0xFFFFFFFFu, t, off));
        if (lane == 0) wmax[0] = t;
    }
    __syncthreads();
    const float absmax = wmax[0];
    const float scale = fmaxf(absmax, EPS) / 127.0f;

    if (tid == 0) g_scales[token] = scale;

    const float inv = 1.0f / scale;
    float vals[8] = {v0.x, v0.y, v0.z, v0.w, v1.x, v1.y, v1.z, v1.w};
    uint32_t p0 = 0, p1 = 0;
    #pragma unroll
    for (int i = 0; i < 4; i++) {
        float q = rintf(vals[i] * inv);
        q = fminf(fmaxf(q, -128.0f), 127.0f);
        int qi = (int)q;
        p0 |= ((uint32_t)(qi & 0xFF)) << (8 * i);
    }
    #pragma unroll
    for (int i = 0; i < 4; i++) {
        float q = rintf(vals[4 + i] * inv);
        q = fminf(fmaxf(q, -128.0f), 127.0f);
        int qi = (int)q;
        p1 |= ((uint32_t)(qi & 0xFF)) << (8 * i);
    }
    int2 packed = make_int2((int)p0, (int)p1);
    *reinterpret_cast<int2*>(g_q + (size_t)token * K_DIM + tid * 8) = packed;
}

// ---------------------------------------------------------------------------
// Kernel 2: int8 GEMM with fused dequant epilogue. FLOAT32 output
// (rounded through fp16 to match the fp16 reference exactly).
// ---------------------------------------------------------------------------
#define BK 64
#define SROW 80  // padded smem row stride (bytes)

__device__ __forceinline__ void cp16(int8_t* s, const int8_t* g) {
    unsigned saddr = (unsigned)__cvta_generic_to_shared(s);
    asm volatile("cp.async.cg.shared.global [%0], [%1], 16;\n" :: "r"(saddr), "l"(g));
}

__global__ __launch_bounds__(256) void gemm_kernel(const float* __restrict__ w_scale,
                                                   const float* __restrict__ bias,
                                                   float* __restrict__ out) {
    __shared__ int8_t sA[2][128 * SROW];
    __shared__ int8_t sB[2][128 * SROW];

    const int tid = threadIdx.x;
    const int lane = tid & 31;
    const int warp = tid >> 5;
    const int warpM = warp >> 2;   // 0..1 (64 rows each)
    const int warpN = warp & 3;    // 0..3 (32 cols each)
    const int g = lane >> 2;       // group id 0..7
    const int tg = lane & 3;       // thread in group

    const int rowBase = blockIdx.y * 128;
    const int colBase = blockIdx.x * 128;

    const int8_t* Ag = g_q + (size_t)rowBase * K_DIM;  // [128, K]
    const int8_t* Bg = g_w + (size_t)colBase * K_DIM;  // [128, K]

    int acc[4][4][4];
    #pragma unroll
    for (int mi = 0; mi < 4; mi++)
        #pragma unroll
        for (int ni = 0; ni < 4; ni++)
            #pragma unroll
            for (int r = 0; r < 4; r++) acc[mi][ni][r] = 0;

    const int KT = K_DIM / BK;  // 32

    // Stage-0 prefetch
    {
        #pragma unroll
        for (int it = 0; it < 2; it++) {
            int c = tid + it * 256;        // 0..511
            int r = c >> 2, kc = (c & 3) * 16;
            cp16(&sA[0][r * SROW + kc], Ag + (size_t)r * K_DIM + kc);
            cp16(&sB[0][r * SROW + kc], Bg + (size_t)r * K_DIM + kc);
        }
        asm volatile("cp.async.commit_group;\n");
    }

    for (int kt = 0; kt < KT; kt++) {
        if (kt + 1 < KT) {
            int k0 = (kt + 1) * BK;
            int buf = (kt + 1) & 1;
            #pragma unroll
            for (int it = 0; it < 2; it++) {
                int c = tid + it * 256;
                int r = c >> 2, kc = (c & 3) * 16;
                cp16(&sA[buf][r * SROW + kc], Ag + (size_t)r * K_DIM + k0 + kc);
                cp16(&sB[buf][r * SROW + kc], Bg + (size_t)r * K_DIM + k0 + kc);
            }
            asm volatile("cp.async.commit_group;\n");
            asm volatile("cp.async.wait_group 1;\n");
        } else {
            asm volatile("cp.async.wait_group 0;\n");
        }
        __syncthreads();

        const int8_t* a = sA[kt & 1];
        const int8_t* b = sB[kt & 1];

        #pragma unroll
        for (int ks = 0; ks < 2; ks++) {
            uint32_t afr[4][4];
            #pragma unroll
            for (int mi = 0; mi < 4; mi++) {
                const int row = warpM * 64 + mi * 16 + g;
                const int8_t* ap = a + row * SROW + ks * 32 + tg * 4;
                afr[mi][0] = *reinterpret_cast<const uint32_t*>(ap);
                afr[mi][1] = *reinterpret_cast<const uint32_t*>(ap + 8 * SROW);
                afr[mi][2] = *reinterpret_cast<const uint32_t*>(ap + 16);
                afr[mi][3] = *reinterpret_cast<const uint32_t*>(ap + 8 * SROW + 16);
            }
            uint32_t bfr[4][2];
            #pragma unroll
            for (int ni = 0; ni < 4; ni++) {
                const int col = warpN * 32 + ni * 8 + g;
                const int8_t* bp = b + col * SROW + ks * 32 + tg * 4;
                bfr[ni][0] = *reinterpret_cast<const uint32_t*>(bp);
                bfr[ni][1] = *reinterpret_cast<const uint32_t*>(bp + 16);
            }
            #pragma unroll
            for (int mi = 0; mi < 4; mi++)
                #pragma unroll
                for (int ni = 0; ni < 4; ni++) {
                    asm volatile(
                        "mma.sync.aligned.m16n8k32.row.col.s32.s8.s8.s32 "
                        "{%0,%1,%2,%3}, {%4,%5,%6,%7}, {%8,%9}, {%0,%1,%2,%3};\n"
                        : "+r"(acc[mi][ni][0]), "+r"(acc[mi][ni][1]),
                          "+r"(acc[mi][ni][2]), "+r"(acc[mi][ni][3])
                        : "r"(afr[mi][0]), "r"(afr[mi][1]), "r"(afr[mi][2]), "r"(afr[mi][3]),
                          "r"(bfr[ni][0]), "r"(bfr[ni][1]));
                }
        }
        __syncthreads();
    }

    // Epilogue: dequant + bias, round to fp16 precision, store as FLOAT32.
    #pragma unroll
    for (int mi = 0; mi < 4; mi++) {
        const int r0 = rowBase + warpM * 64 + mi * 16 + g;
        const float s0 = g_scales[r0];
        const float s1 = g_scales[r0 + 8];
        #pragma unroll
        for (int ni = 0; ni < 4; ni++) {
            const int c = colBase + warpN * 32 + ni * 8 + tg * 2;
            const float w0 = w_scale[c];
            const float w1 = w_scale[c + 1];
            const float b0 = bias[c];
            const float b1 = bias[c + 1];

            float2 o0, o1;
            o0.x = __half2float(__float2half_rn((float)acc[mi][ni][0] * s0 * w0 + b0));
            o0.y = __half2float(__float2half_rn((float)acc[mi][ni][1] * s0 * w1 + b1));
            o1.x = __half2float(__float2half_rn((float)acc[mi][ni][2] * s1 * w0 + b0));
            o1.y = __half2float(__float2half_rn((float)acc[mi][ni][3] * s1 * w1 + b1));

            *reinterpret_cast<float2*>(out + (size_t)r0 * N_DIM + c) = o0;
            *reinterpret_cast<float2*>(out + (size_t)(r0 + 8) * N_DIM + c) = o1;
        }
    }
}

extern "C" void kernel_launch(void* const* d_in, const int* in_sizes, int n_in,
                              void* d_out, int out_size) {
    const float* x       = (const float*)d_in[0];
    const int*   weight  = (const int*)d_in[1];   // int8 marshalled as int32
    const float* w_scale = (const float*)d_in[2];
    const float* bias    = (const float*)d_in[3];
    float* out = (float*)d_out;

    pack_w_kernel<<<(N_DIM * K_DIM / 4) / 256, 256>>>(weight);
    quant_kernel<<<M_TOKENS, 256>>>(x);
    dim3 grid(N_DIM / 128, M_TOKENS / 128);
    gemm_kernel<<<grid, 256>>>(w_scale, bias, out);
}